// round 1
// baseline (speedup 1.0000x reference)
#include <cuda_runtime.h>
#include <cuda_bf16.h>
#include <math.h>

#define D 64
#define K 64
#define EPSV 1e-8f

// Global scratch (no allocation allowed)
__device__ float g_colsum[K];
__device__ float g_distsum[K];
__device__ int   g_count[K];

__global__ void zero_scratch_kernel() {
    int t = threadIdx.x;
    if (t < K) {
        g_colsum[t]  = 0.0f;
        g_distsum[t] = 0.0f;
        g_count[t]   = 0;
    }
}

// Warp-per-row main pass: column sums of assignments, per-row argmax,
// distance to own center, per-cluster dist-sum and count.
__global__ void __launch_bounds__(256) cluster_main_kernel(
    const float* __restrict__ z,       // [B, 64]
    const float* __restrict__ a,       // [B, 64]
    const float* __restrict__ centers, // [64, 64]
    int B)
{
    __shared__ float sc[K * D];     // centers, 16 KB
    __shared__ float s_col[K];
    __shared__ float s_dist[K];
    __shared__ int   s_cnt[K];

    int tid = threadIdx.x;
    for (int i = tid; i < K * D; i += blockDim.x) sc[i] = centers[i];
    if (tid < K) { s_col[tid] = 0.0f; s_dist[tid] = 0.0f; s_cnt[tid] = 0; }
    __syncthreads();

    const int lane = tid & 31;
    const int warp = tid >> 5;
    const int wpb  = blockDim.x >> 5;
    long long gwarp  = (long long)blockIdx.x * wpb + warp;
    long long nwarps = (long long)gridDim.x * wpb;

    // Lane l owns columns 2l and 2l+1 for the column sums (register-resident).
    float acc0 = 0.0f, acc1 = 0.0f;

    for (long long row = gwarp; row < B; row += nwarps) {
        const float2 av = __ldg((const float2*)(a + row * D) + lane);
        acc0 += av.x;
        acc1 += av.y;

        // per-lane best of its two columns (first-max tiebreak: lower index)
        float bv; int bi;
        if (av.y > av.x) { bv = av.y; bi = 2 * lane + 1; }
        else             { bv = av.x; bi = 2 * lane;     }
        // warp argmax reduce
        #pragma unroll
        for (int off = 16; off > 0; off >>= 1) {
            float ov = __shfl_down_sync(0xffffffffu, bv, off);
            int   oi = __shfl_down_sync(0xffffffffu, bi, off);
            if (ov > bv || (ov == bv && oi < bi)) { bv = ov; bi = oi; }
        }
        bi = __shfl_sync(0xffffffffu, bi, 0);

        // distance to assigned center
        const float2 zv = __ldg((const float2*)(z + row * D) + lane);
        const float2 cv = *((const float2*)(sc + bi * D) + lane);
        float dx = zv.x - cv.x;
        float dy = zv.y - cv.y;
        float s = dx * dx + dy * dy;
        #pragma unroll
        for (int off = 16; off > 0; off >>= 1)
            s += __shfl_down_sync(0xffffffffu, s, off);

        if (lane == 0) {
            atomicAdd(&s_dist[bi], sqrtf(s));
            atomicAdd(&s_cnt[bi], 1);
        }
    }

    // fold register column sums into block-shared
    atomicAdd(&s_col[2 * lane],     acc0);
    atomicAdd(&s_col[2 * lane + 1], acc1);
    __syncthreads();

    if (tid < K) {
        atomicAdd(&g_colsum[tid],  s_col[tid]);
        atomicAdd(&g_distsum[tid], s_dist[tid]);
        atomicAdd(&g_count[tid],   s_cnt[tid]);
    }
}

// Single-block finalize: separation (4096 pairs), balance KL, compactness,
// unbiased std, weighted sum. Writes the 5 output scalars.
__global__ void __launch_bounds__(256) finalize_kernel(
    const float* __restrict__ centers, float* __restrict__ out, int B)
{
    __shared__ float red[256];
    int tid = threadIdx.x;

    // separation: sum of off-diagonal pairwise center distances
    float part = 0.0f;
    for (int p = tid; p < K * K; p += 256) {
        int i = p >> 6, j = p & 63;
        if (i != j) {
            float s = 0.0f;
            #pragma unroll 8
            for (int d = 0; d < D; d++) {
                float df = centers[i * D + d] - centers[j * D + d];
                s += df * df;
            }
            part += (s > 0.0f) ? sqrtf(s) : 0.0f;
        }
    }
    red[tid] = part;
    __syncthreads();
    for (int off = 128; off > 0; off >>= 1) {
        if (tid < off) red[tid] += red[tid + off];
        __syncthreads();
    }

    if (tid == 0) {
        const float sep = -red[0] / (float)(K * (K - 1));

        const float u = 1.0f / (float)K;
        const float logu = logf(u);
        float bal = 0.0f;
        float mean = 0.0f;
        float probs[K];
        for (int k = 0; k < K; k++) {
            float p = g_colsum[k] / (float)B;
            probs[k] = p;
            bal  += u * (logu - logf(p + EPSV));
            mean += p;
        }
        mean /= (float)K;
        float var = 0.0f;
        for (int k = 0; k < K; k++) {
            float dv = probs[k] - mean;
            var += dv * dv;
        }
        var /= (float)(K - 1);
        const float cb = sqrtf(var);

        float comp = 0.0f;
        int nn = 0;
        for (int k = 0; k < K; k++) {
            if (g_count[k] > 0) {
                comp += g_distsum[k] / (float)g_count[k];
                nn++;
            }
        }
        comp = comp / (float)(nn > 0 ? nn : 1);

        const float aux = 0.1f * bal + 0.1f * sep + 0.1f * comp;
        out[0] = aux;
        out[1] = bal;
        out[2] = sep;
        out[3] = comp;
        out[4] = cb;
    }
}

extern "C" void kernel_launch(void* const* d_in, const int* in_sizes, int n_in,
                              void* d_out, int out_size)
{
    const float* latent_z  = (const float*)d_in[0];
    const float* assigns   = (const float*)d_in[1];
    const float* centers   = (const float*)d_in[2];
    float* out = (float*)d_out;

    const int B = in_sizes[0] / D;

    zero_scratch_kernel<<<1, 64>>>();

    const int threads = 256;
    const int blocks  = 2048;
    cluster_main_kernel<<<blocks, threads>>>(latent_z, assigns, centers, B);

    finalize_kernel<<<1, 256>>>(centers, out, B);
}

// round 3
// speedup vs baseline: 1.4785x; 1.4785x over previous
#include <cuda_runtime.h>
#include <cuda_bf16.h>
#include <math.h>

#define D 64
#define K 64
#define EPSV 1e-8f
#define NBLK 2048

// Per-block partials: [block][0:64)=colsum, [64:128)=distsum, [128:192)=count
__device__ float g_part[NBLK * 192];

__global__ void __launch_bounds__(256) cluster_main_kernel(
    const float* __restrict__ z,       // [B, 64]
    const float* __restrict__ a,       // [B, 64]
    const float* __restrict__ centers, // [64, 64]
    int B)
{
    __shared__ float sc[K * D];     // centers, 16 KB
    __shared__ float s_col[K];
    __shared__ float s_dist[K];
    __shared__ float s_cnt[K];

    const int tid = threadIdx.x;
    for (int i = tid; i < K * D; i += 256) sc[i] = centers[i];
    if (tid < K) { s_col[tid] = 0.0f; s_dist[tid] = 0.0f; s_cnt[tid] = 0.0f; }
    __syncthreads();

    const int lane = tid & 31;
    const int warp = tid >> 5;
    const int sub  = lane >> 3;        // which of 4 rows in this warp-iteration
    const int sl   = lane & 7;         // lane within subwarp
    const int colbase = sl * 8;        // this thread owns columns colbase..colbase+7

    const long long gwarp  = (long long)blockIdx.x * 8 + warp;
    const long long stride = (long long)gridDim.x * 8 * 4;

    // register-resident column sums for the 8 owned columns
    float c0=0,c1=0,c2=0,c3=0,c4=0,c5=0,c6=0,c7=0;

    for (long long base = gwarp * 4; base < B; base += stride) {
        const long long row = base + sub;
        const bool valid = (row < B);
        const long long r = valid ? row : (long long)(B - 1);

        const float4* ap = (const float4*)(a + r * D + colbase);
        const float4  a0 = __ldcs(ap);
        const float4  a1 = __ldcs(ap + 1);
        const float4* zp = (const float4*)(z + r * D + colbase);
        const float4  z0 = __ldcs(zp);
        const float4  z1 = __ldcs(zp + 1);

        if (valid) {
            c0 += a0.x; c1 += a0.y; c2 += a0.z; c3 += a0.w;
            c4 += a1.x; c5 += a1.y; c6 += a1.z; c7 += a1.w;
        }

        // thread-local argmax over 8 columns (strict > : lowest index wins ties)
        float bv = a0.x; int bi = colbase;
        if (a0.y > bv) { bv = a0.y; bi = colbase + 1; }
        if (a0.z > bv) { bv = a0.z; bi = colbase + 2; }
        if (a0.w > bv) { bv = a0.w; bi = colbase + 3; }
        if (a1.x > bv) { bv = a1.x; bi = colbase + 4; }
        if (a1.y > bv) { bv = a1.y; bi = colbase + 5; }
        if (a1.z > bv) { bv = a1.z; bi = colbase + 6; }
        if (a1.w > bv) { bv = a1.w; bi = colbase + 7; }

        // Packed-key subwarp argmax (values are positive floats -> bit pattern
        // ordering == value ordering). Low 32 bits hold (63 - idx) so the max
        // key resolves value ties toward the LOWEST index.
        unsigned long long key =
            ((unsigned long long)__float_as_uint(bv) << 32) |
            (unsigned long long)(63 - bi);
        #pragma unroll
        for (int off = 4; off > 0; off >>= 1) {
            unsigned long long ok = __shfl_xor_sync(0xffffffffu, key, off, 8);
            if (ok > key) key = ok;
        }
        const int best = 63 - (int)(key & 0xffffffffull);

        // distance to assigned center (8 owned dims)
        const float4* cp = (const float4*)(sc + best * D + colbase);
        const float4 cc0 = cp[0];
        const float4 cc1 = cp[1];
        float s = 0.0f, dx;
        dx = z0.x - cc0.x; s = fmaf(dx, dx, s);
        dx = z0.y - cc0.y; s = fmaf(dx, dx, s);
        dx = z0.z - cc0.z; s = fmaf(dx, dx, s);
        dx = z0.w - cc0.w; s = fmaf(dx, dx, s);
        dx = z1.x - cc1.x; s = fmaf(dx, dx, s);
        dx = z1.y - cc1.y; s = fmaf(dx, dx, s);
        dx = z1.z - cc1.z; s = fmaf(dx, dx, s);
        dx = z1.w - cc1.w; s = fmaf(dx, dx, s);
        #pragma unroll
        for (int off = 4; off > 0; off >>= 1)
            s += __shfl_xor_sync(0xffffffffu, s, off, 8);

        if (sl == 0 && valid) {
            atomicAdd(&s_dist[best], sqrtf(s));
            atomicAdd(&s_cnt[best], 1.0f);
        }
    }

    // fold register column sums into block-shared
    atomicAdd(&s_col[colbase + 0], c0);
    atomicAdd(&s_col[colbase + 1], c1);
    atomicAdd(&s_col[colbase + 2], c2);
    atomicAdd(&s_col[colbase + 3], c3);
    atomicAdd(&s_col[colbase + 4], c4);
    atomicAdd(&s_col[colbase + 5], c5);
    atomicAdd(&s_col[colbase + 6], c6);
    atomicAdd(&s_col[colbase + 7], c7);
    __syncthreads();

    // every block writes all 192 slots unconditionally -> no pre-zero needed
    if (tid < 192) {
        float v = (tid < 64) ? s_col[tid]
                : (tid < 128) ? s_dist[tid - 64]
                : s_cnt[tid - 128];
        g_part[(long long)blockIdx.x * 192 + tid] = v;
    }
}

// Single-block finalize: reduce block partials, separation (4096 pairs),
// balance KL, compactness, unbiased std, weighted sum.
__global__ void __launch_bounds__(256) finalize_kernel(
    const float* __restrict__ centers, float* __restrict__ out, int B)
{
    __shared__ float sc[K * D];
    __shared__ float slot[192];
    __shared__ float red[256];
    const int tid = threadIdx.x;

    for (int i = tid; i < K * D; i += 256) sc[i] = centers[i];

    if (tid < 192) {
        float s = 0.0f;
        #pragma unroll 8
        for (int b = 0; b < NBLK; b++) s += g_part[(long long)b * 192 + tid];
        slot[tid] = s;
    }
    __syncthreads();

    // separation: sum of off-diagonal pairwise center distances
    float part = 0.0f;
    for (int p = tid; p < K * K; p += 256) {
        const int i = p >> 6, j = p & 63;
        if (i != j) {
            float s = 0.0f;
            #pragma unroll
            for (int d = 0; d < D; d++) {
                const float df = sc[i * D + d] - sc[j * D + d];
                s = fmaf(df, df, s);
            }
            part += (s > 0.0f) ? sqrtf(s) : 0.0f;
        }
    }
    red[tid] = part;
    __syncthreads();
    for (int off = 128; off > 0; off >>= 1) {
        if (tid < off) red[tid] += red[tid + off];
        __syncthreads();
    }

    if (tid == 0) {
        const float sep = -red[0] / (float)(K * (K - 1));

        const float u = 1.0f / (float)K;
        const float logu = logf(u);
        float bal = 0.0f, mean = 0.0f;
        float probs[K];
        for (int k = 0; k < K; k++) {
            const float p = slot[k] / (float)B;
            probs[k] = p;
            bal  += u * (logu - logf(p + EPSV));
            mean += p;
        }
        mean /= (float)K;
        float var = 0.0f;
        for (int k = 0; k < K; k++) {
            const float dv = probs[k] - mean;
            var += dv * dv;
        }
        var /= (float)(K - 1);
        const float cb = sqrtf(var);

        float comp = 0.0f;
        int nn = 0;
        for (int k = 0; k < K; k++) {
            const float cnt = slot[128 + k];
            if (cnt > 0.0f) {
                comp += slot[64 + k] / cnt;
                nn++;
            }
        }
        comp /= (float)(nn > 0 ? nn : 1);

        const float aux = 0.1f * bal + 0.1f * sep + 0.1f * comp;
        out[0] = aux;
        out[1] = bal;
        out[2] = sep;
        out[3] = comp;
        out[4] = cb;
    }
}

extern "C" void kernel_launch(void* const* d_in, const int* in_sizes, int n_in,
                              void* d_out, int out_size)
{
    const float* latent_z = (const float*)d_in[0];
    const float* assigns  = (const float*)d_in[1];
    const float* centers  = (const float*)d_in[2];
    float* out = (float*)d_out;

    const int B = in_sizes[0] / D;

    cluster_main_kernel<<<NBLK, 256>>>(latent_z, assigns, centers, B);
    finalize_kernel<<<1, 256>>>(centers, out, B);
}

// round 5
// speedup vs baseline: 1.9816x; 1.3402x over previous
#include <cuda_runtime.h>
#include <cuda_bf16.h>
#include <math.h>

#define D 64
#define K 64
#define EPSV 1e-8f
#define NBLK 1184   // 148 SMs x 8 blocks: exactly one resident wave

// Global accumulators: [0:64)=colsum, [64:128)=distsum, [128:192)=count
__device__ float g_acc[192];

__global__ void zero_acc_kernel() {
    if (threadIdx.x < 192) g_acc[threadIdx.x] = 0.0f;
}

__global__ void __launch_bounds__(256) cluster_main_kernel(
    const float* __restrict__ z,       // [B, 64]
    const float* __restrict__ a,       // [B, 64]
    const float* __restrict__ centers, // [64, 64]
    int B)
{
    __shared__ float sc[K * D];     // centers, 16 KB
    __shared__ float s_col[K];
    __shared__ float s_dist[K];
    __shared__ float s_cnt[K];

    const int tid = threadIdx.x;
    for (int i = tid; i < K * D; i += 256) sc[i] = centers[i];
    if (tid < K) { s_col[tid] = 0.0f; s_dist[tid] = 0.0f; s_cnt[tid] = 0.0f; }
    __syncthreads();

    const int lane = tid & 31;
    const int warp = tid >> 5;
    const int sub  = lane >> 3;        // which of 4 rows in this warp-iteration
    const int sl   = lane & 7;         // lane within subwarp
    const int colbase = sl * 8;        // this thread owns columns colbase..colbase+7

    const long long gwarp  = (long long)blockIdx.x * 8 + warp;
    const long long stride = (long long)gridDim.x * 8 * 4;

    // register-resident column sums for the 8 owned columns
    float c0=0,c1=0,c2=0,c3=0,c4=0,c5=0,c6=0,c7=0;

    for (long long base = gwarp * 4; base < B; base += stride) {
        const long long row = base + sub;
        const bool valid = (row < B);
        const long long r = valid ? row : (long long)(B - 1);

        const float4* ap = (const float4*)(a + r * D + colbase);
        const float4  a0 = __ldcs(ap);
        const float4  a1 = __ldcs(ap + 1);
        const float4* zp = (const float4*)(z + r * D + colbase);
        const float4  z0 = __ldcs(zp);
        const float4  z1 = __ldcs(zp + 1);

        if (valid) {
            c0 += a0.x; c1 += a0.y; c2 += a0.z; c3 += a0.w;
            c4 += a1.x; c5 += a1.y; c6 += a1.z; c7 += a1.w;
        }

        // thread-local argmax over 8 columns (strict > : lowest index wins ties)
        float bv = a0.x; int bi = colbase;
        if (a0.y > bv) { bv = a0.y; bi = colbase + 1; }
        if (a0.z > bv) { bv = a0.z; bi = colbase + 2; }
        if (a0.w > bv) { bv = a0.w; bi = colbase + 3; }
        if (a1.x > bv) { bv = a1.x; bi = colbase + 4; }
        if (a1.y > bv) { bv = a1.y; bi = colbase + 5; }
        if (a1.z > bv) { bv = a1.z; bi = colbase + 6; }
        if (a1.w > bv) { bv = a1.w; bi = colbase + 7; }

        // Packed-key subwarp argmax (values are positive floats -> bit pattern
        // ordering == value ordering). Low 32 bits hold (63 - idx) so the max
        // key resolves value ties toward the LOWEST index.
        unsigned long long key =
            ((unsigned long long)__float_as_uint(bv) << 32) |
            (unsigned long long)(63 - bi);
        #pragma unroll
        for (int off = 4; off > 0; off >>= 1) {
            unsigned long long ok = __shfl_xor_sync(0xffffffffu, key, off, 8);
            if (ok > key) key = ok;
        }
        const int best = 63 - (int)(key & 0xffffffffull);

        // distance to assigned center (8 owned dims)
        const float4* cp = (const float4*)(sc + best * D + colbase);
        const float4 cc0 = cp[0];
        const float4 cc1 = cp[1];
        float s = 0.0f, dx;
        dx = z0.x - cc0.x; s = fmaf(dx, dx, s);
        dx = z0.y - cc0.y; s = fmaf(dx, dx, s);
        dx = z0.z - cc0.z; s = fmaf(dx, dx, s);
        dx = z0.w - cc0.w; s = fmaf(dx, dx, s);
        dx = z1.x - cc1.x; s = fmaf(dx, dx, s);
        dx = z1.y - cc1.y; s = fmaf(dx, dx, s);
        dx = z1.z - cc1.z; s = fmaf(dx, dx, s);
        dx = z1.w - cc1.w; s = fmaf(dx, dx, s);
        #pragma unroll
        for (int off = 4; off > 0; off >>= 1)
            s += __shfl_xor_sync(0xffffffffu, s, off, 8);

        if (sl == 0 && valid) {
            atomicAdd(&s_dist[best], sqrtf(s));
            atomicAdd(&s_cnt[best], 1.0f);
        }
    }

    // fold register column sums into block-shared
    atomicAdd(&s_col[colbase + 0], c0);
    atomicAdd(&s_col[colbase + 1], c1);
    atomicAdd(&s_col[colbase + 2], c2);
    atomicAdd(&s_col[colbase + 3], c3);
    atomicAdd(&s_col[colbase + 4], c4);
    atomicAdd(&s_col[colbase + 5], c5);
    atomicAdd(&s_col[colbase + 6], c6);
    atomicAdd(&s_col[colbase + 7], c7);
    __syncthreads();

    // one global atomic per slot per block (192 spread addresses, cheap)
    if (tid < 192) {
        const float v = (tid < 64) ? s_col[tid]
                      : (tid < 128) ? s_dist[tid - 64]
                      : s_cnt[tid - 128];
        atomicAdd(&g_acc[tid], v);
    }
}

// Single-block finalize: separation (4096 pairs), balance KL, compactness,
// unbiased std, weighted sum.
__global__ void __launch_bounds__(256) finalize_kernel(
    const float* __restrict__ centers, float* __restrict__ out, int B)
{
    __shared__ float sc[K * D];
    __shared__ float red[256];
    const int tid = threadIdx.x;

    for (int i = tid; i < K * D; i += 256) sc[i] = centers[i];
    __syncthreads();

    // separation: sum of off-diagonal pairwise center distances
    float part = 0.0f;
    for (int p = tid; p < K * K; p += 256) {
        const int i = p >> 6, j = p & 63;
        if (i != j) {
            float s = 0.0f;
            #pragma unroll
            for (int d = 0; d < D; d++) {
                const float df = sc[i * D + d] - sc[j * D + d];
                s = fmaf(df, df, s);
            }
            part += (s > 0.0f) ? sqrtf(s) : 0.0f;
        }
    }
    red[tid] = part;
    __syncthreads();
    for (int off = 128; off > 0; off >>= 1) {
        if (tid < off) red[tid] += red[tid + off];
        __syncthreads();
    }

    if (tid == 0) {
        const float sep = -red[0] / (float)(K * (K - 1));

        const float u = 1.0f / (float)K;
        const float logu = logf(u);
        float bal = 0.0f, mean = 0.0f;
        float probs[K];
        for (int k = 0; k < K; k++) {
            const float p = g_acc[k] / (float)B;
            probs[k] = p;
            bal  += u * (logu - logf(p + EPSV));
            mean += p;
        }
        mean /= (float)K;
        float var = 0.0f;
        for (int k = 0; k < K; k++) {
            const float dv = probs[k] - mean;
            var += dv * dv;
        }
        var /= (float)(K - 1);
        const float cb = sqrtf(var);

        float comp = 0.0f;
        int nn = 0;
        for (int k = 0; k < K; k++) {
            const float cnt = g_acc[128 + k];
            if (cnt > 0.0f) {
                comp += g_acc[64 + k] / cnt;
                nn++;
            }
        }
        comp /= (float)(nn > 0 ? nn : 1);

        const float aux = 0.1f * bal + 0.1f * sep + 0.1f * comp;
        out[0] = aux;
        out[1] = bal;
        out[2] = sep;
        out[3] = comp;
        out[4] = cb;
    }
}

extern "C" void kernel_launch(void* const* d_in, const int* in_sizes, int n_in,
                              void* d_out, int out_size)
{
    const float* latent_z = (const float*)d_in[0];
    const float* assigns  = (const float*)d_in[1];
    const float* centers  = (const float*)d_in[2];
    float* out = (float*)d_out;

    const int B = in_sizes[0] / D;

    zero_acc_kernel<<<1, 192>>>();
    cluster_main_kernel<<<NBLK, 256>>>(latent_z, assigns, centers, B);
    finalize_kernel<<<1, 256>>>(centers, out, B);
}

// round 7
// speedup vs baseline: 2.1713x; 1.0958x over previous
#include <cuda_runtime.h>
#include <cuda_bf16.h>
#include <math.h>

#define D 64
#define K 64
#define EPSV 1e-8f
#define NBLK 1184   // 148 SMs x 8 blocks

// Global accumulators: [0:64)=colsum, [64:128)=distsum, [128:192)=count
__device__ float g_acc[192];

__global__ void zero_acc_kernel() {
    if (threadIdx.x < 192) g_acc[threadIdx.x] = 0.0f;
}

__global__ void __launch_bounds__(256) cluster_main_kernel(
    const float* __restrict__ z,       // [B, 64]
    const float* __restrict__ a,       // [B, 64]
    const float* __restrict__ centers, // [64, 64]
    int B)
{
    __shared__ float sc[K * D];     // centers, 16 KB
    __shared__ float s_col[K];
    __shared__ float s_dist[K];
    __shared__ float s_cnt[K];

    const int tid = threadIdx.x;
    for (int i = tid; i < K * D; i += 256) sc[i] = centers[i];
    if (tid < K) { s_col[tid] = 0.0f; s_dist[tid] = 0.0f; s_cnt[tid] = 0.0f; }
    __syncthreads();

    const int lane = tid & 31;
    const int warp = tid >> 5;
    const int sub  = lane >> 3;        // which of 4 rows in this warp-iteration
    const int sl   = lane & 7;         // lane within subwarp
    // Dense-load column ownership: columns [4sl, 4sl+4) and [32+4sl, 32+4sl+4).
    // A warp-wide LDG.128 at offset sl*16 within a 128B row-half is fully
    // contiguous: 4 rows x 128B = 4 complete cache lines, no wasted sectors.
    const int cb0 = sl * 4;
    const int cb1 = 32 + sl * 4;

    const long long gwarp  = (long long)blockIdx.x * 8 + warp;
    const long long stride = (long long)gridDim.x * 8 * 4;

    // register-resident column sums for the 8 owned columns
    float c0=0,c1=0,c2=0,c3=0,c4=0,c5=0,c6=0,c7=0;

    for (long long base = gwarp * 4; base < B; base += stride) {
        const long long row = base + sub;
        const bool valid = (row < B);
        const long long r = valid ? row : (long long)(B - 1);

        const float4  a0 = __ldcs((const float4*)(a + r * D + cb0));
        const float4  a1 = __ldcs((const float4*)(a + r * D + cb1));
        const float4  z0 = __ldcs((const float4*)(z + r * D + cb0));
        const float4  z1 = __ldcs((const float4*)(z + r * D + cb1));

        if (valid) {
            c0 += a0.x; c1 += a0.y; c2 += a0.z; c3 += a0.w;
            c4 += a1.x; c5 += a1.y; c6 += a1.z; c7 += a1.w;
        }

        // thread-local argmax over 8 columns (strict > : lowest index wins ties)
        float bv = a0.x; int bi = cb0;
        if (a0.y > bv) { bv = a0.y; bi = cb0 + 1; }
        if (a0.z > bv) { bv = a0.z; bi = cb0 + 2; }
        if (a0.w > bv) { bv = a0.w; bi = cb0 + 3; }
        if (a1.x > bv) { bv = a1.x; bi = cb1;     }
        if (a1.y > bv) { bv = a1.y; bi = cb1 + 1; }
        if (a1.z > bv) { bv = a1.z; bi = cb1 + 2; }
        if (a1.w > bv) { bv = a1.w; bi = cb1 + 3; }

        // Packed-key subwarp argmax (values are positive floats -> bit pattern
        // ordering == value ordering). Low 32 bits hold (63 - idx) so the max
        // key resolves value ties toward the LOWEST index.
        unsigned long long key =
            ((unsigned long long)__float_as_uint(bv) << 32) |
            (unsigned long long)(63 - bi);
        #pragma unroll
        for (int off = 4; off > 0; off >>= 1) {
            unsigned long long ok = __shfl_xor_sync(0xffffffffu, key, off, 8);
            if (ok > key) key = ok;
        }
        const int best = 63 - (int)(key & 0xffffffffull);

        // distance to assigned center (8 owned dims; LDS is conflict-free:
        // lane sl hits banks 4sl..4sl+3 within each 8-lane phase)
        const float4 cc0 = *(const float4*)(sc + best * D + cb0);
        const float4 cc1 = *(const float4*)(sc + best * D + cb1);
        float s = 0.0f, dx;
        dx = z0.x - cc0.x; s = fmaf(dx, dx, s);
        dx = z0.y - cc0.y; s = fmaf(dx, dx, s);
        dx = z0.z - cc0.z; s = fmaf(dx, dx, s);
        dx = z0.w - cc0.w; s = fmaf(dx, dx, s);
        dx = z1.x - cc1.x; s = fmaf(dx, dx, s);
        dx = z1.y - cc1.y; s = fmaf(dx, dx, s);
        dx = z1.z - cc1.z; s = fmaf(dx, dx, s);
        dx = z1.w - cc1.w; s = fmaf(dx, dx, s);
        #pragma unroll
        for (int off = 4; off > 0; off >>= 1)
            s += __shfl_xor_sync(0xffffffffu, s, off, 8);

        if (sl == 0 && valid) {
            atomicAdd(&s_dist[best], sqrtf(s));
            atomicAdd(&s_cnt[best], 1.0f);
        }
    }

    // fold register column sums into block-shared
    atomicAdd(&s_col[cb0 + 0], c0);
    atomicAdd(&s_col[cb0 + 1], c1);
    atomicAdd(&s_col[cb0 + 2], c2);
    atomicAdd(&s_col[cb0 + 3], c3);
    atomicAdd(&s_col[cb1 + 0], c4);
    atomicAdd(&s_col[cb1 + 1], c5);
    atomicAdd(&s_col[cb1 + 2], c6);
    atomicAdd(&s_col[cb1 + 3], c7);
    __syncthreads();

    // one global atomic per slot per block (192 spread addresses, cheap)
    if (tid < 192) {
        const float v = (tid < 64) ? s_col[tid]
                      : (tid < 128) ? s_dist[tid - 64]
                      : s_cnt[tid - 128];
        atomicAdd(&g_acc[tid], v);
    }
}

// Single-block finalize: separation (4096 pairs), balance KL, compactness,
// unbiased std, weighted sum.
__global__ void __launch_bounds__(256) finalize_kernel(
    const float* __restrict__ centers, float* __restrict__ out, int B)
{
    __shared__ float sc[K * D];
    __shared__ float red[256];
    const int tid = threadIdx.x;

    for (int i = tid; i < K * D; i += 256) sc[i] = centers[i];
    __syncthreads();

    // separation: sum of off-diagonal pairwise center distances
    float part = 0.0f;
    for (int p = tid; p < K * K; p += 256) {
        const int i = p >> 6, j = p & 63;
        if (i != j) {
            float s = 0.0f;
            #pragma unroll
            for (int d = 0; d < D; d++) {
                const float df = sc[i * D + d] - sc[j * D + d];
                s = fmaf(df, df, s);
            }
            part += (s > 0.0f) ? sqrtf(s) : 0.0f;
        }
    }
    red[tid] = part;
    __syncthreads();
    for (int off = 128; off > 0; off >>= 1) {
        if (tid < off) red[tid] += red[tid + off];
        __syncthreads();
    }

    if (tid == 0) {
        const float sep = -red[0] / (float)(K * (K - 1));

        const float u = 1.0f / (float)K;
        const float logu = logf(u);
        float bal = 0.0f, mean = 0.0f;
        float probs[K];
        for (int k = 0; k < K; k++) {
            const float p = g_acc[k] / (float)B;
            probs[k] = p;
            bal  += u * (logu - logf(p + EPSV));
            mean += p;
        }
        mean /= (float)K;
        float var = 0.0f;
        for (int k = 0; k < K; k++) {
            const float dv = probs[k] - mean;
            var += dv * dv;
        }
        var /= (float)(K - 1);
        const float cb = sqrtf(var);

        float comp = 0.0f;
        int nn = 0;
        for (int k = 0; k < K; k++) {
            const float cnt = g_acc[128 + k];
            if (cnt > 0.0f) {
                comp += g_acc[64 + k] / cnt;
                nn++;
            }
        }
        comp /= (float)(nn > 0 ? nn : 1);

        const float aux = 0.1f * bal + 0.1f * sep + 0.1f * comp;
        out[0] = aux;
        out[1] = bal;
        out[2] = sep;
        out[3] = comp;
        out[4] = cb;
    }
}

extern "C" void kernel_launch(void* const* d_in, const int* in_sizes, int n_in,
                              void* d_out, int out_size)
{
    const float* latent_z = (const float*)d_in[0];
    const float* assigns  = (const float*)d_in[1];
    const float* centers  = (const float*)d_in[2];
    float* out = (float*)d_out;

    const int B = in_sizes[0] / D;

    zero_acc_kernel<<<1, 192>>>();
    cluster_main_kernel<<<NBLK, 256>>>(latent_z, assigns, centers, B);
    finalize_kernel<<<1, 256>>>(centers, out, B);
}

// round 9
// speedup vs baseline: 2.4236x; 1.1162x over previous
#include <cuda_runtime.h>
#include <cuda_bf16.h>
#include <math.h>

#define D 64
#define K 64
#define EPSV 1e-8f
#define NBLK 1184   // 148 SMs x 8 blocks

// Global accumulators: [0:64)=colsum, [64:128)=distsum, [128:192)=count
// Statically zero-initialized; finalize_kernel re-zeroes after reading, so
// every kernel_launch (and every graph replay) starts from zeros.
__device__ float g_acc[192];

__global__ void __launch_bounds__(256) cluster_main_kernel(
    const float* __restrict__ z,       // [B, 64]
    const float* __restrict__ a,       // [B, 64]
    const float* __restrict__ centers, // [64, 64]
    int B)
{
    __shared__ float sc[K * D];     // centers, 16 KB
    __shared__ float s_col[K];
    __shared__ float s_dist[K];
    __shared__ float s_cnt[K];

    const int tid = threadIdx.x;
    for (int i = tid; i < K * D; i += 256) sc[i] = centers[i];
    if (tid < K) { s_col[tid] = 0.0f; s_dist[tid] = 0.0f; s_cnt[tid] = 0.0f; }
    __syncthreads();

    const int lane = tid & 31;
    const int warp = tid >> 5;
    const int sub  = lane >> 3;        // row within a 4-row group
    const int sl   = lane & 7;         // lane within subwarp
    const int cb0 = sl * 4;            // owned columns [cb0, cb0+4)
    const int cb1 = 32 + sl * 4;       // and [cb1, cb1+4)

    const int gwarp  = blockIdx.x * 8 + warp;
    const int stride = NBLK * 8 * 8;   // warps * 8 rows each per iteration

    float c0=0,c1=0,c2=0,c3=0,c4=0,c5=0,c6=0,c7=0;

    for (int base = gwarp * 8; base < B; base += stride) {
        // two 4-row groups; issue all 8 global loads up front (MLP=8)
        const int rowA = base + sub;
        const int rowB = base + 4 + sub;
        const bool vA = (rowA < B);
        const bool vB = (rowB < B);
        const int rA = vA ? rowA : (B - 1);
        const int rB = vB ? rowB : (B - 1);

        const float4 aA0 = __ldcs((const float4*)(a + rA * D + cb0));
        const float4 aA1 = __ldcs((const float4*)(a + rA * D + cb1));
        const float4 aB0 = __ldcs((const float4*)(a + rB * D + cb0));
        const float4 aB1 = __ldcs((const float4*)(a + rB * D + cb1));
        const float4 zA0 = __ldcs((const float4*)(z + rA * D + cb0));
        const float4 zA1 = __ldcs((const float4*)(z + rA * D + cb1));
        const float4 zB0 = __ldcs((const float4*)(z + rB * D + cb0));
        const float4 zB1 = __ldcs((const float4*)(z + rB * D + cb1));

        // ---- group A ----
        if (vA) {
            c0 += aA0.x; c1 += aA0.y; c2 += aA0.z; c3 += aA0.w;
            c4 += aA1.x; c5 += aA1.y; c6 += aA1.z; c7 += aA1.w;
        }
        {
            float bv = aA0.x; int bi = cb0;
            if (aA0.y > bv) { bv = aA0.y; bi = cb0 + 1; }
            if (aA0.z > bv) { bv = aA0.z; bi = cb0 + 2; }
            if (aA0.w > bv) { bv = aA0.w; bi = cb0 + 3; }
            if (aA1.x > bv) { bv = aA1.x; bi = cb1;     }
            if (aA1.y > bv) { bv = aA1.y; bi = cb1 + 1; }
            if (aA1.z > bv) { bv = aA1.z; bi = cb1 + 2; }
            if (aA1.w > bv) { bv = aA1.w; bi = cb1 + 3; }
            unsigned long long key =
                ((unsigned long long)__float_as_uint(bv) << 32) |
                (unsigned long long)(63 - bi);
            #pragma unroll
            for (int off = 4; off > 0; off >>= 1) {
                unsigned long long ok = __shfl_xor_sync(0xffffffffu, key, off, 8);
                if (ok > key) key = ok;
            }
            const int best = 63 - (int)(key & 0xffffffffull);

            const float4 cc0 = *(const float4*)(sc + best * D + cb0);
            const float4 cc1 = *(const float4*)(sc + best * D + cb1);
            float s = 0.0f, dx;
            dx = zA0.x - cc0.x; s = fmaf(dx, dx, s);
            dx = zA0.y - cc0.y; s = fmaf(dx, dx, s);
            dx = zA0.z - cc0.z; s = fmaf(dx, dx, s);
            dx = zA0.w - cc0.w; s = fmaf(dx, dx, s);
            dx = zA1.x - cc1.x; s = fmaf(dx, dx, s);
            dx = zA1.y - cc1.y; s = fmaf(dx, dx, s);
            dx = zA1.z - cc1.z; s = fmaf(dx, dx, s);
            dx = zA1.w - cc1.w; s = fmaf(dx, dx, s);
            #pragma unroll
            for (int off = 4; off > 0; off >>= 1)
                s += __shfl_xor_sync(0xffffffffu, s, off, 8);
            if (sl == 0 && vA) {
                atomicAdd(&s_dist[best], sqrtf(s));
                atomicAdd(&s_cnt[best], 1.0f);
            }
        }

        // ---- group B ----
        if (vB) {
            c0 += aB0.x; c1 += aB0.y; c2 += aB0.z; c3 += aB0.w;
            c4 += aB1.x; c5 += aB1.y; c6 += aB1.z; c7 += aB1.w;
        }
        {
            float bv = aB0.x; int bi = cb0;
            if (aB0.y > bv) { bv = aB0.y; bi = cb0 + 1; }
            if (aB0.z > bv) { bv = aB0.z; bi = cb0 + 2; }
            if (aB0.w > bv) { bv = aB0.w; bi = cb0 + 3; }
            if (aB1.x > bv) { bv = aB1.x; bi = cb1;     }
            if (aB1.y > bv) { bv = aB1.y; bi = cb1 + 1; }
            if (aB1.z > bv) { bv = aB1.z; bi = cb1 + 2; }
            if (aB1.w > bv) { bv = aB1.w; bi = cb1 + 3; }
            unsigned long long key =
                ((unsigned long long)__float_as_uint(bv) << 32) |
                (unsigned long long)(63 - bi);
            #pragma unroll
            for (int off = 4; off > 0; off >>= 1) {
                unsigned long long ok = __shfl_xor_sync(0xffffffffu, key, off, 8);
                if (ok > key) key = ok;
            }
            const int best = 63 - (int)(key & 0xffffffffull);

            const float4 cc0 = *(const float4*)(sc + best * D + cb0);
            const float4 cc1 = *(const float4*)(sc + best * D + cb1);
            float s = 0.0f, dx;
            dx = zB0.x - cc0.x; s = fmaf(dx, dx, s);
            dx = zB0.y - cc0.y; s = fmaf(dx, dx, s);
            dx = zB0.z - cc0.z; s = fmaf(dx, dx, s);
            dx = zB0.w - cc0.w; s = fmaf(dx, dx, s);
            dx = zB1.x - cc1.x; s = fmaf(dx, dx, s);
            dx = zB1.y - cc1.y; s = fmaf(dx, dx, s);
            dx = zB1.z - cc1.z; s = fmaf(dx, dx, s);
            dx = zB1.w - cc1.w; s = fmaf(dx, dx, s);
            #pragma unroll
            for (int off = 4; off > 0; off >>= 1)
                s += __shfl_xor_sync(0xffffffffu, s, off, 8);
            if (sl == 0 && vB) {
                atomicAdd(&s_dist[best], sqrtf(s));
                atomicAdd(&s_cnt[best], 1.0f);
            }
        }
    }

    // fold register column sums into block-shared
    atomicAdd(&s_col[cb0 + 0], c0);
    atomicAdd(&s_col[cb0 + 1], c1);
    atomicAdd(&s_col[cb0 + 2], c2);
    atomicAdd(&s_col[cb0 + 3], c3);
    atomicAdd(&s_col[cb1 + 0], c4);
    atomicAdd(&s_col[cb1 + 1], c5);
    atomicAdd(&s_col[cb1 + 2], c6);
    atomicAdd(&s_col[cb1 + 3], c7);
    __syncthreads();

    // one global atomic per slot per block (192 spread addresses, cheap)
    if (tid < 192) {
        const float v = (tid < 64) ? s_col[tid]
                      : (tid < 128) ? s_dist[tid - 64]
                      : s_cnt[tid - 128];
        atomicAdd(&g_acc[tid], v);
    }
}

// Single-block finalize: separation (4096 pairs), balance KL, compactness,
// unbiased std, weighted sum. Also resets g_acc for the next replay.
__global__ void __launch_bounds__(256) finalize_kernel(
    const float* __restrict__ centers, float* __restrict__ out, int B)
{
    __shared__ float sc[K * D];
    __shared__ float slot[192];
    __shared__ float red[256];
    const int tid = threadIdx.x;

    for (int i = tid; i < K * D; i += 256) sc[i] = centers[i];
    if (tid < 192) {
        slot[tid] = g_acc[tid];
        g_acc[tid] = 0.0f;          // reset for next replay (deterministic)
    }
    __syncthreads();

    // separation: sum of off-diagonal pairwise center distances
    float part = 0.0f;
    for (int p = tid; p < K * K; p += 256) {
        const int i = p >> 6, j = p & 63;
        if (i != j) {
            float s = 0.0f;
            #pragma unroll
            for (int d = 0; d < D; d++) {
                const float df = sc[i * D + d] - sc[j * D + d];
                s = fmaf(df, df, s);
            }
            part += (s > 0.0f) ? sqrtf(s) : 0.0f;
        }
    }
    red[tid] = part;
    __syncthreads();
    for (int off = 128; off > 0; off >>= 1) {
        if (tid < off) red[tid] += red[tid + off];
        __syncthreads();
    }

    if (tid == 0) {
        const float sep = -red[0] / (float)(K * (K - 1));

        const float u = 1.0f / (float)K;
        const float logu = logf(u);
        float bal = 0.0f, mean = 0.0f;
        float probs[K];
        for (int k = 0; k < K; k++) {
            const float p = slot[k] / (float)B;
            probs[k] = p;
            bal  += u * (logu - logf(p + EPSV));
            mean += p;
        }
        mean /= (float)K;
        float var = 0.0f;
        for (int k = 0; k < K; k++) {
            const float dv = probs[k] - mean;
            var += dv * dv;
        }
        var /= (float)(K - 1);
        const float cb = sqrtf(var);

        float comp = 0.0f;
        int nn = 0;
        for (int k = 0; k < K; k++) {
            const float cnt = slot[128 + k];
            if (cnt > 0.0f) {
                comp += slot[64 + k] / cnt;
                nn++;
            }
        }
        comp /= (float)(nn > 0 ? nn : 1);

        const float aux = 0.1f * bal + 0.1f * sep + 0.1f * comp;
        out[0] = aux;
        out[1] = bal;
        out[2] = sep;
        out[3] = comp;
        out[4] = cb;
    }
}

extern "C" void kernel_launch(void* const* d_in, const int* in_sizes, int n_in,
                              void* d_out, int out_size)
{
    const float* latent_z = (const float*)d_in[0];
    const float* assigns  = (const float*)d_in[1];
    const float* centers  = (const float*)d_in[2];
    float* out = (float*)d_out;

    const int B = in_sizes[0] / D;

    cluster_main_kernel<<<NBLK, 256>>>(latent_z, assigns, centers, B);
    finalize_kernel<<<1, 256>>>(centers, out, B);
}

// round 11
// speedup vs baseline: 3.2587x; 1.3446x over previous
#include <cuda_runtime.h>
#include <cuda_bf16.h>
#include <math.h>

#define D 64
#define K 64
#define EPSV 1e-8f
#define NBLK 1184   // 148 SMs x 8 blocks

// Global accumulators: [0:64)=colsum, [64:128)=distsum, [128:192)=count
// Statically zero-initialized; finalize_kernel re-zeroes after reading, so
// every kernel_launch (and every graph replay) starts from zeros.
__device__ float g_acc[192];

__global__ void __launch_bounds__(256) cluster_main_kernel(
    const float* __restrict__ z,       // [B, 64]
    const float* __restrict__ a,       // [B, 64]
    const float* __restrict__ centers, // [64, 64]
    int B)
{
    __shared__ float sc[K * D];     // centers, 16 KB
    __shared__ float s_col[K];
    __shared__ float s_dist[K];
    __shared__ float s_cnt[K];

    const int tid = threadIdx.x;
    for (int i = tid; i < K * D; i += 256) sc[i] = centers[i];
    if (tid < K) { s_col[tid] = 0.0f; s_dist[tid] = 0.0f; s_cnt[tid] = 0.0f; }
    __syncthreads();

    const int lane = tid & 31;
    const int warp = tid >> 5;
    const int sub  = lane >> 3;        // row within a 4-row group
    const int sl   = lane & 7;         // lane within subwarp
    const int cb0 = sl * 4;            // owned columns [cb0, cb0+4)
    const int cb1 = 32 + sl * 4;       // and [cb1, cb1+4)

    const int gwarp  = blockIdx.x * 8 + warp;
    const int stride = NBLK * 8 * 8;   // warps * 8 rows each per iteration

    float c0=0,c1=0,c2=0,c3=0,c4=0,c5=0,c6=0,c7=0;

    for (int base = gwarp * 8; base < B; base += stride) {
        // two 4-row groups; issue all 8 global loads up front (MLP=8)
        const int rowA = base + sub;
        const int rowB = base + 4 + sub;
        const bool vA = (rowA < B);
        const bool vB = (rowB < B);
        const int rA = vA ? rowA : (B - 1);
        const int rB = vB ? rowB : (B - 1);

        const float4 aA0 = __ldcs((const float4*)(a + rA * D + cb0));
        const float4 aA1 = __ldcs((const float4*)(a + rA * D + cb1));
        const float4 aB0 = __ldcs((const float4*)(a + rB * D + cb0));
        const float4 aB1 = __ldcs((const float4*)(a + rB * D + cb1));
        const float4 zA0 = __ldcs((const float4*)(z + rA * D + cb0));
        const float4 zA1 = __ldcs((const float4*)(z + rA * D + cb1));
        const float4 zB0 = __ldcs((const float4*)(z + rB * D + cb0));
        const float4 zB1 = __ldcs((const float4*)(z + rB * D + cb1));

        // ---- group A ----
        if (vA) {
            c0 += aA0.x; c1 += aA0.y; c2 += aA0.z; c3 += aA0.w;
            c4 += aA1.x; c5 += aA1.y; c6 += aA1.z; c7 += aA1.w;
        }
        {
            float bv = aA0.x; int bi = cb0;
            if (aA0.y > bv) { bv = aA0.y; bi = cb0 + 1; }
            if (aA0.z > bv) { bv = aA0.z; bi = cb0 + 2; }
            if (aA0.w > bv) { bv = aA0.w; bi = cb0 + 3; }
            if (aA1.x > bv) { bv = aA1.x; bi = cb1;     }
            if (aA1.y > bv) { bv = aA1.y; bi = cb1 + 1; }
            if (aA1.z > bv) { bv = aA1.z; bi = cb1 + 2; }
            if (aA1.w > bv) { bv = aA1.w; bi = cb1 + 3; }
            unsigned long long key =
                ((unsigned long long)__float_as_uint(bv) << 32) |
                (unsigned long long)(63 - bi);
            #pragma unroll
            for (int off = 4; off > 0; off >>= 1) {
                unsigned long long ok = __shfl_xor_sync(0xffffffffu, key, off, 8);
                if (ok > key) key = ok;
            }
            const int best = 63 - (int)(key & 0xffffffffull);

            const float4 cc0 = *(const float4*)(sc + best * D + cb0);
            const float4 cc1 = *(const float4*)(sc + best * D + cb1);
            float s = 0.0f, dx;
            dx = zA0.x - cc0.x; s = fmaf(dx, dx, s);
            dx = zA0.y - cc0.y; s = fmaf(dx, dx, s);
            dx = zA0.z - cc0.z; s = fmaf(dx, dx, s);
            dx = zA0.w - cc0.w; s = fmaf(dx, dx, s);
            dx = zA1.x - cc1.x; s = fmaf(dx, dx, s);
            dx = zA1.y - cc1.y; s = fmaf(dx, dx, s);
            dx = zA1.z - cc1.z; s = fmaf(dx, dx, s);
            dx = zA1.w - cc1.w; s = fmaf(dx, dx, s);
            #pragma unroll
            for (int off = 4; off > 0; off >>= 1)
                s += __shfl_xor_sync(0xffffffffu, s, off, 8);
            if (sl == 0 && vA) {
                atomicAdd(&s_dist[best], sqrtf(s));
                atomicAdd(&s_cnt[best], 1.0f);
            }
        }

        // ---- group B ----
        if (vB) {
            c0 += aB0.x; c1 += aB0.y; c2 += aB0.z; c3 += aB0.w;
            c4 += aB1.x; c5 += aB1.y; c6 += aB1.z; c7 += aB1.w;
        }
        {
            float bv = aB0.x; int bi = cb0;
            if (aB0.y > bv) { bv = aB0.y; bi = cb0 + 1; }
            if (aB0.z > bv) { bv = aB0.z; bi = cb0 + 2; }
            if (aB0.w > bv) { bv = aB0.w; bi = cb0 + 3; }
            if (aB1.x > bv) { bv = aB1.x; bi = cb1;     }
            if (aB1.y > bv) { bv = aB1.y; bi = cb1 + 1; }
            if (aB1.z > bv) { bv = aB1.z; bi = cb1 + 2; }
            if (aB1.w > bv) { bv = aB1.w; bi = cb1 + 3; }
            unsigned long long key =
                ((unsigned long long)__float_as_uint(bv) << 32) |
                (unsigned long long)(63 - bi);
            #pragma unroll
            for (int off = 4; off > 0; off >>= 1) {
                unsigned long long ok = __shfl_xor_sync(0xffffffffu, key, off, 8);
                if (ok > key) key = ok;
            }
            const int best = 63 - (int)(key & 0xffffffffull);

            const float4 cc0 = *(const float4*)(sc + best * D + cb0);
            const float4 cc1 = *(const float4*)(sc + best * D + cb1);
            float s = 0.0f, dx;
            dx = zB0.x - cc0.x; s = fmaf(dx, dx, s);
            dx = zB0.y - cc0.y; s = fmaf(dx, dx, s);
            dx = zB0.z - cc0.z; s = fmaf(dx, dx, s);
            dx = zB0.w - cc0.w; s = fmaf(dx, dx, s);
            dx = zB1.x - cc1.x; s = fmaf(dx, dx, s);
            dx = zB1.y - cc1.y; s = fmaf(dx, dx, s);
            dx = zB1.z - cc1.z; s = fmaf(dx, dx, s);
            dx = zB1.w - cc1.w; s = fmaf(dx, dx, s);
            #pragma unroll
            for (int off = 4; off > 0; off >>= 1)
                s += __shfl_xor_sync(0xffffffffu, s, off, 8);
            if (sl == 0 && vB) {
                atomicAdd(&s_dist[best], sqrtf(s));
                atomicAdd(&s_cnt[best], 1.0f);
            }
        }
    }

    // fold register column sums into block-shared
    atomicAdd(&s_col[cb0 + 0], c0);
    atomicAdd(&s_col[cb0 + 1], c1);
    atomicAdd(&s_col[cb0 + 2], c2);
    atomicAdd(&s_col[cb0 + 3], c3);
    atomicAdd(&s_col[cb1 + 0], c4);
    atomicAdd(&s_col[cb1 + 1], c5);
    atomicAdd(&s_col[cb1 + 2], c6);
    atomicAdd(&s_col[cb1 + 3], c7);
    __syncthreads();

    // one global atomic per slot per block (192 spread addresses, cheap)
    if (tid < 192) {
        const float v = (tid < 64) ? s_col[tid]
                      : (tid < 128) ? s_dist[tid - 64]
                      : s_cnt[tid - 128];
        atomicAdd(&g_acc[tid], v);
    }
}

// Single-block finalize. Separation uses lane-rotated float4 LDS (conflict-
// free); the scalar tail is warp-parallel with butterfly reductions.
// Also resets g_acc for the next replay.
__global__ void __launch_bounds__(256) finalize_kernel(
    const float* __restrict__ centers, float* __restrict__ out, int B)
{
    __shared__ float sc[K * D];
    __shared__ float slot[192];
    __shared__ float red[256];
    const int tid  = threadIdx.x;
    const int lane = tid & 31;

    for (int i = tid; i < K * D; i += 256) sc[i] = centers[i];
    if (tid < 192) {
        slot[tid] = g_acc[tid];
        g_acc[tid] = 0.0f;          // reset for next replay (deterministic)
    }
    __syncthreads();

    // separation: off-diagonal pairwise center distances.
    // Lane-rotated float4 chunks: within each 16-lane LDS phase every lane
    // reads a distinct 16B bank-group -> conflict-free.
    float part = 0.0f;
    for (int p = tid; p < K * K; p += 256) {
        const int i = p >> 6, j = p & 63;
        if (i != j) {
            const float4* ci = (const float4*)(sc + i * D);
            const float4* cj = (const float4*)(sc + j * D);
            float s = 0.0f;
            #pragma unroll
            for (int t = 0; t < 16; t++) {
                const int d4 = (t + lane) & 15;
                const float4 x = ci[d4];
                const float4 y = cj[d4];
                float dx;
                dx = x.x - y.x; s = fmaf(dx, dx, s);
                dx = x.y - y.y; s = fmaf(dx, dx, s);
                dx = x.z - y.z; s = fmaf(dx, dx, s);
                dx = x.w - y.w; s = fmaf(dx, dx, s);
            }
            part += (s > 0.0f) ? sqrtf(s) : 0.0f;
        }
    }
    red[tid] = part;
    __syncthreads();
    for (int off = 128; off > 0; off >>= 1) {
        if (tid < off) red[tid] += red[tid + off];
        __syncthreads();
    }

    // warp 0: balance / compactness / std, 2 clusters per lane
    if (tid < 32) {
        const float invB = 1.0f / (float)B;
        const float u = 1.0f / (float)K;
        const float logu = logf(u);

        const float p0 = slot[lane]      * invB;
        const float p1 = slot[lane + 32] * invB;
        float bal  = u * (logu - logf(p0 + EPSV))
                   + u * (logu - logf(p1 + EPSV));
        float msum = p0 + p1;

        const float cnt0 = slot[128 + lane];
        const float cnt1 = slot[160 + lane];
        float comp = 0.0f, nn = 0.0f;
        if (cnt0 > 0.0f) { comp += slot[64 + lane] / cnt0; nn += 1.0f; }
        if (cnt1 > 0.0f) { comp += slot[96 + lane] / cnt1; nn += 1.0f; }

        // butterfly reductions (all lanes end with totals)
        #pragma unroll
        for (int off = 16; off > 0; off >>= 1) {
            bal  += __shfl_xor_sync(0xffffffffu, bal,  off);
            msum += __shfl_xor_sync(0xffffffffu, msum, off);
            comp += __shfl_xor_sync(0xffffffffu, comp, off);
            nn   += __shfl_xor_sync(0xffffffffu, nn,   off);
        }
        const float mean = msum / (float)K;
        float var = (p0 - mean) * (p0 - mean) + (p1 - mean) * (p1 - mean);
        #pragma unroll
        for (int off = 16; off > 0; off >>= 1)
            var += __shfl_xor_sync(0xffffffffu, var, off);

        if (lane == 0) {
            const float sep = -red[0] / (float)(K * (K - 1));
            const float cb  = sqrtf(var / (float)(K - 1));
            comp = comp / ((nn > 0.0f) ? nn : 1.0f);
            const float aux = 0.1f * bal + 0.1f * sep + 0.1f * comp;
            out[0] = aux;
            out[1] = bal;
            out[2] = sep;
            out[3] = comp;
            out[4] = cb;
        }
    }
}

extern "C" void kernel_launch(void* const* d_in, const int* in_sizes, int n_in,
                              void* d_out, int out_size)
{
    const float* latent_z = (const float*)d_in[0];
    const float* assigns  = (const float*)d_in[1];
    const float* centers  = (const float*)d_in[2];
    float* out = (float*)d_out;

    const int B = in_sizes[0] / D;

    cluster_main_kernel<<<NBLK, 256>>>(latent_z, assigns, centers, B);
    finalize_kernel<<<1, 256>>>(centers, out, B);
}

// round 12
// speedup vs baseline: 3.6963x; 1.1343x over previous
#include <cuda_runtime.h>
#include <cuda_bf16.h>
#include <math.h>

#define D 64
#define K 64
#define EPSV 1e-8f
#define NBLK 1184   // 148 SMs x 8 blocks: exactly one resident wave

// Global accumulators: [0:64)=colsum, [64:128)=distsum, [128:192)=count,
// [192]=separation sum (written by the dedicated sep block each launch).
// Statically zero-initialized; finalize_kernel re-zeroes 0..191 after reading.
__device__ float g_acc[193];

__global__ void __launch_bounds__(256) cluster_main_kernel(
    const float* __restrict__ z,       // [B, 64]
    const float* __restrict__ a,       // [B, 64]
    const float* __restrict__ centers, // [64, 64]
    int B)
{
    __shared__ float sc[K * D];     // centers, 16 KB
    __shared__ float s_col[K];
    __shared__ float s_dist[K];
    __shared__ float s_cnt[K];
    __shared__ float red[256];

    const int tid  = threadIdx.x;
    const int lane = tid & 31;

    for (int i = tid; i < K * D; i += 256) sc[i] = centers[i];

    // ---------- dedicated separation block (overlaps the streaming pass) ----------
    if (blockIdx.x == gridDim.x - 1) {
        __syncthreads();
        float part = 0.0f;
        for (int p = tid; p < K * K; p += 256) {
            const int i = p >> 6, j = p & 63;
            if (i != j) {
                const float4* ci = (const float4*)(sc + i * D);
                const float4* cj = (const float4*)(sc + j * D);
                float s = 0.0f;
                #pragma unroll
                for (int t = 0; t < 16; t++) {
                    const int d4 = (t + lane) & 15;   // conflict-free rotation
                    const float4 x = ci[d4];
                    const float4 y = cj[d4];
                    float dx;
                    dx = x.x - y.x; s = fmaf(dx, dx, s);
                    dx = x.y - y.y; s = fmaf(dx, dx, s);
                    dx = x.z - y.z; s = fmaf(dx, dx, s);
                    dx = x.w - y.w; s = fmaf(dx, dx, s);
                }
                part += (s > 0.0f) ? sqrtf(s) : 0.0f;
            }
        }
        red[tid] = part;
        __syncthreads();
        for (int off = 128; off > 0; off >>= 1) {
            if (tid < off) red[tid] += red[tid + off];
            __syncthreads();
        }
        if (tid == 0) g_acc[192] = red[0];   // plain store: single writer
        return;
    }

    // ---------- streaming blocks ----------
    if (tid < K) { s_col[tid] = 0.0f; s_dist[tid] = 0.0f; s_cnt[tid] = 0.0f; }
    __syncthreads();

    const int warp = tid >> 5;
    const int sub  = lane >> 3;        // row within a 4-row group
    const int sl   = lane & 7;         // lane within subwarp
    const int cb0 = sl * 4;            // owned columns [cb0, cb0+4)
    const int cb1 = 32 + sl * 4;       // and [cb1, cb1+4)

    const int nstream = NBLK - 1;      // 1183 streaming blocks
    const int gwarp   = blockIdx.x * 8 + warp;
    const int stride  = nstream * 8 * 8;

    float c0=0,c1=0,c2=0,c3=0,c4=0,c5=0,c6=0,c7=0;

    for (int base = gwarp * 8; base < B; base += stride) {
        const int rowA = base + sub;
        const int rowB = base + 4 + sub;
        const bool vA = (rowA < B);
        const bool vB = (rowB < B);
        const int rA = vA ? rowA : (B - 1);
        const int rB = vB ? rowB : (B - 1);

        const float4 aA0 = __ldcs((const float4*)(a + rA * D + cb0));
        const float4 aA1 = __ldcs((const float4*)(a + rA * D + cb1));
        const float4 aB0 = __ldcs((const float4*)(a + rB * D + cb0));
        const float4 aB1 = __ldcs((const float4*)(a + rB * D + cb1));
        const float4 zA0 = __ldcs((const float4*)(z + rA * D + cb0));
        const float4 zA1 = __ldcs((const float4*)(z + rA * D + cb1));
        const float4 zB0 = __ldcs((const float4*)(z + rB * D + cb0));
        const float4 zB1 = __ldcs((const float4*)(z + rB * D + cb1));

        // ---- group A ----
        if (vA) {
            c0 += aA0.x; c1 += aA0.y; c2 += aA0.z; c3 += aA0.w;
            c4 += aA1.x; c5 += aA1.y; c6 += aA1.z; c7 += aA1.w;
        }
        {
            float bv = aA0.x; int bi = cb0;
            if (aA0.y > bv) { bv = aA0.y; bi = cb0 + 1; }
            if (aA0.z > bv) { bv = aA0.z; bi = cb0 + 2; }
            if (aA0.w > bv) { bv = aA0.w; bi = cb0 + 3; }
            if (aA1.x > bv) { bv = aA1.x; bi = cb1;     }
            if (aA1.y > bv) { bv = aA1.y; bi = cb1 + 1; }
            if (aA1.z > bv) { bv = aA1.z; bi = cb1 + 2; }
            if (aA1.w > bv) { bv = aA1.w; bi = cb1 + 3; }
            unsigned long long key =
                ((unsigned long long)__float_as_uint(bv) << 32) |
                (unsigned long long)(63 - bi);
            #pragma unroll
            for (int off = 4; off > 0; off >>= 1) {
                unsigned long long ok = __shfl_xor_sync(0xffffffffu, key, off, 8);
                if (ok > key) key = ok;
            }
            const int best = 63 - (int)(key & 0xffffffffull);

            const float4 cc0 = *(const float4*)(sc + best * D + cb0);
            const float4 cc1 = *(const float4*)(sc + best * D + cb1);
            float s = 0.0f, dx;
            dx = zA0.x - cc0.x; s = fmaf(dx, dx, s);
            dx = zA0.y - cc0.y; s = fmaf(dx, dx, s);
            dx = zA0.z - cc0.z; s = fmaf(dx, dx, s);
            dx = zA0.w - cc0.w; s = fmaf(dx, dx, s);
            dx = zA1.x - cc1.x; s = fmaf(dx, dx, s);
            dx = zA1.y - cc1.y; s = fmaf(dx, dx, s);
            dx = zA1.z - cc1.z; s = fmaf(dx, dx, s);
            dx = zA1.w - cc1.w; s = fmaf(dx, dx, s);
            #pragma unroll
            for (int off = 4; off > 0; off >>= 1)
                s += __shfl_xor_sync(0xffffffffu, s, off, 8);
            if (sl == 0 && vA) {
                atomicAdd(&s_dist[best], sqrtf(s));
                atomicAdd(&s_cnt[best], 1.0f);
            }
        }

        // ---- group B ----
        if (vB) {
            c0 += aB0.x; c1 += aB0.y; c2 += aB0.z; c3 += aB0.w;
            c4 += aB1.x; c5 += aB1.y; c6 += aB1.z; c7 += aB1.w;
        }
        {
            float bv = aB0.x; int bi = cb0;
            if (aB0.y > bv) { bv = aB0.y; bi = cb0 + 1; }
            if (aB0.z > bv) { bv = aB0.z; bi = cb0 + 2; }
            if (aB0.w > bv) { bv = aB0.w; bi = cb0 + 3; }
            if (aB1.x > bv) { bv = aB1.x; bi = cb1;     }
            if (aB1.y > bv) { bv = aB1.y; bi = cb1 + 1; }
            if (aB1.z > bv) { bv = aB1.z; bi = cb1 + 2; }
            if (aB1.w > bv) { bv = aB1.w; bi = cb1 + 3; }
            unsigned long long key =
                ((unsigned long long)__float_as_uint(bv) << 32) |
                (unsigned long long)(63 - bi);
            #pragma unroll
            for (int off = 4; off > 0; off >>= 1) {
                unsigned long long ok = __shfl_xor_sync(0xffffffffu, key, off, 8);
                if (ok > key) key = ok;
            }
            const int best = 63 - (int)(key & 0xffffffffull);

            const float4 cc0 = *(const float4*)(sc + best * D + cb0);
            const float4 cc1 = *(const float4*)(sc + best * D + cb1);
            float s = 0.0f, dx;
            dx = zB0.x - cc0.x; s = fmaf(dx, dx, s);
            dx = zB0.y - cc0.y; s = fmaf(dx, dx, s);
            dx = zB0.z - cc0.z; s = fmaf(dx, dx, s);
            dx = zB0.w - cc0.w; s = fmaf(dx, dx, s);
            dx = zB1.x - cc1.x; s = fmaf(dx, dx, s);
            dx = zB1.y - cc1.y; s = fmaf(dx, dx, s);
            dx = zB1.z - cc1.z; s = fmaf(dx, dx, s);
            dx = zB1.w - cc1.w; s = fmaf(dx, dx, s);
            #pragma unroll
            for (int off = 4; off > 0; off >>= 1)
                s += __shfl_xor_sync(0xffffffffu, s, off, 8);
            if (sl == 0 && vB) {
                atomicAdd(&s_dist[best], sqrtf(s));
                atomicAdd(&s_cnt[best], 1.0f);
            }
        }
    }

    // fold register column sums into block-shared
    atomicAdd(&s_col[cb0 + 0], c0);
    atomicAdd(&s_col[cb0 + 1], c1);
    atomicAdd(&s_col[cb0 + 2], c2);
    atomicAdd(&s_col[cb0 + 3], c3);
    atomicAdd(&s_col[cb1 + 0], c4);
    atomicAdd(&s_col[cb1 + 1], c5);
    atomicAdd(&s_col[cb1 + 2], c6);
    atomicAdd(&s_col[cb1 + 3], c7);
    __syncthreads();

    // one global atomic per slot per block (192 spread addresses, cheap)
    if (tid < 192) {
        const float v = (tid < 64) ? s_col[tid]
                      : (tid < 128) ? s_dist[tid - 64]
                      : s_cnt[tid - 128];
        atomicAdd(&g_acc[tid], v);
    }
}

// Tiny finalize: read 193 accumulators, warp-parallel scalar tail.
// Resets g_acc[0:192) for the next replay.
__global__ void __launch_bounds__(64) finalize_kernel(
    float* __restrict__ out, int B)
{
    __shared__ float slot[193];
    const int tid  = threadIdx.x;
    const int lane = tid & 31;

    for (int i = tid; i < 193; i += 64) {
        slot[i] = g_acc[i];
        if (i < 192) g_acc[i] = 0.0f;   // reset for next replay
    }
    __syncthreads();

    if (tid < 32) {
        const float invB = 1.0f / (float)B;
        const float u = 1.0f / (float)K;
        const float logu = logf(u);

        const float p0 = slot[lane]      * invB;
        const float p1 = slot[lane + 32] * invB;
        float bal  = u * (logu - logf(p0 + EPSV))
                   + u * (logu - logf(p1 + EPSV));
        float msum = p0 + p1;

        const float cnt0 = slot[128 + lane];
        const float cnt1 = slot[160 + lane];
        float comp = 0.0f, nn = 0.0f;
        if (cnt0 > 0.0f) { comp += slot[64 + lane] / cnt0; nn += 1.0f; }
        if (cnt1 > 0.0f) { comp += slot[96 + lane] / cnt1; nn += 1.0f; }

        #pragma unroll
        for (int off = 16; off > 0; off >>= 1) {
            bal  += __shfl_xor_sync(0xffffffffu, bal,  off);
            msum += __shfl_xor_sync(0xffffffffu, msum, off);
            comp += __shfl_xor_sync(0xffffffffu, comp, off);
            nn   += __shfl_xor_sync(0xffffffffu, nn,   off);
        }
        const float mean = msum / (float)K;
        float var = (p0 - mean) * (p0 - mean) + (p1 - mean) * (p1 - mean);
        #pragma unroll
        for (int off = 16; off > 0; off >>= 1)
            var += __shfl_xor_sync(0xffffffffu, var, off);

        if (lane == 0) {
            const float sep = -slot[192] / (float)(K * (K - 1));
            const float cb  = sqrtf(var / (float)(K - 1));
            comp = comp / ((nn > 0.0f) ? nn : 1.0f);
            const float aux = 0.1f * bal + 0.1f * sep + 0.1f * comp;
            out[0] = aux;
            out[1] = bal;
            out[2] = sep;
            out[3] = comp;
            out[4] = cb;
        }
    }
}

extern "C" void kernel_launch(void* const* d_in, const int* in_sizes, int n_in,
                              void* d_out, int out_size)
{
    const float* latent_z = (const float*)d_in[0];
    const float* assigns  = (const float*)d_in[1];
    const float* centers  = (const float*)d_in[2];
    float* out = (float*)d_out;

    const int B = in_sizes[0] / D;

    cluster_main_kernel<<<NBLK, 256>>>(latent_z, assigns, centers, B);
    finalize_kernel<<<1, 64>>>(out, B);
}